// round 12
// baseline (speedup 1.0000x reference)
#include <cuda_runtime.h>
#include <cstdint>

// Fixed problem: x [256,2048,7,7] fp32, x0 [256,49,1] fp32, out scalar fp32
#define BATCH   256
#define NQ      4                     // K-split partials per batch
#define NCTA    (BATCH * NQ)          // 1024
#define KQ      512                   // channels per CTA
#define KCH     32                    // channels per chunk
#define NCH     (KQ / KCH)            // 16 chunks
#define NDIM    49
#define CHF     (KCH * NDIM)          // 1568 floats per chunk
#define CHB     (CHF * 4)             // 6272 bytes (16B multiple)
#define STAGES  4
#define THREADS 128
#define EPSV    1e-12f

__device__ float g_partial[NCTA][NDIM * NDIM];
__device__ float g_penalty[BATCH];
__device__ int   g_cnt[BATCH];        // zero-init; reset each run
__device__ int   g_cnt_all;

static __device__ __forceinline__ uint32_t smem_u32(const void* p) {
    uint32_t a;
    asm("{ .reg .u64 t; cvta.to.shared.u64 t, %1; cvt.u32.u64 %0, t; }" : "=r"(a) : "l"(p));
    return a;
}

#define MBARRIER_INIT(addr, cnt) \
    asm volatile("mbarrier.init.shared.b64 [%0], %1;" :: "r"(addr), "r"(cnt) : "memory")

#define MBARRIER_EXPECT_TX(addr, bytes) \
    asm volatile("mbarrier.arrive.expect_tx.shared.b64 _, [%0], %1;" \
                 :: "r"(addr), "r"(bytes) : "memory")

#define TMA_BULK_1D(dst, src, bytes, mbar) \
    asm volatile("cp.async.bulk.shared::cta.global.mbarrier::complete_tx::bytes " \
                 "[%0], [%1], %2, [%3];" \
                 :: "r"(dst), "l"(src), "r"(bytes), "r"(mbar) : "memory")

#define MBARRIER_WAIT_PARITY(addr, par) do {                                        \
    uint32_t _m = (addr), _p = (par), _d;                                           \
    asm volatile("{\n\t.reg .pred p;\n\t"                                           \
        "mbarrier.try_wait.parity.acquire.cta.shared::cta.b64 p, [%1], %2;\n\t"     \
        "selp.b32 %0, 1, 0, p;\n\t}"                                                \
        : "=r"(_d) : "r"(_m), "r"(_p) : "memory");                                  \
    if (!_d) {                                                                      \
        asm volatile("{\n\t.reg .pred P1;\n\t"                                      \
            "WL_%=:\n\t"                                                            \
            "mbarrier.try_wait.parity.acquire.cta.shared::cta.b64 P1, [%0], %1, 0x989680;\n\t" \
            "@P1 bra.uni WD_%=;\n\t"                                                \
            "bra.uni WL_%=;\n\t"                                                    \
            "WD_%=:\n\t}"                                                           \
            :: "r"(_m), "r"(_p) : "memory");                                        \
    }                                                                               \
} while (0)

// m16n8k8 tf32 mma on raw fp32 bits (HW truncates to tf32). sm_80 PTX.
static __device__ __forceinline__ void mma8(float* c,
    uint32_t a0, uint32_t a1, uint32_t a2, uint32_t a3,
    uint32_t b0, uint32_t b1)
{
    asm("mma.sync.aligned.m16n8k8.row.col.f32.tf32.tf32.f32 "
        "{%0,%1,%2,%3}, {%4,%5,%6,%7}, {%8,%9}, {%0,%1,%2,%3};"
        : "+f"(c[0]), "+f"(c[1]), "+f"(c[2]), "+f"(c[3])
        : "r"(a0), "r"(a1), "r"(a2), "r"(a3), "r"(b0), "r"(b1));
}

// Block-wide sum over first 49 lanes' values (all 128 threads call).
static __device__ __forceinline__ float reduce49(float v, int t, float* sarr) {
    if (t < 64) sarr[t] = (t < NDIM) ? v : 0.0f;
    __syncthreads();
    if (t < 32) {
        float r = sarr[t] + sarr[t + 32];
        r += __shfl_xor_sync(0xffffffffu, r, 16);
        r += __shfl_xor_sync(0xffffffffu, r, 8);
        r += __shfl_xor_sync(0xffffffffu, r, 4);
        r += __shfl_xor_sync(0xffffffffu, r, 2);
        r += __shfl_xor_sync(0xffffffffu, r, 1);
        if (t == 0) sarr[0] = r;
    }
    __syncthreads();
    float out = sarr[0];
    __syncthreads();
    return out;
}

__global__ void __launch_bounds__(THREADS, 6)
ofp_fused(const float* __restrict__ x, const float* __restrict__ x0,
          float* __restrict__ out)
{
    __shared__ __align__(16) float sbuf[STAGES * CHF + 16];  // +16 pad for frag overreads
    __shared__ __align__(8) unsigned long long mbar[STAGES];
    __shared__ float sx[64];
    __shared__ float sred[64];
    __shared__ int scomm;
    float* sA = sbuf;                         // 2401 floats; buffers dead by PI time

    const int t    = threadIdx.x;
    const int lane = t & 31, wid = t >> 5;
    const int l4   = lane & 3, ld4 = lane >> 2;
    const int cta  = blockIdx.x;
    const int b    = cta >> 2, q = cta & 3;
    const int qm   = wid >> 1, qn = wid & 1;  // warp's 32x32 quadrant
    const int m0   = qm * 32 + ld4;
    const int n0f  = qn * 32 + ld4;

    const float* __restrict__ xq =
        x + (size_t)b * (2048 * NDIM) + (size_t)q * (KQ * NDIM);

    const uint32_t sbase = smem_u32(sbuf);
    const uint32_t mbase = smem_u32(mbar);

    // init barriers + zero the overread pad tail
    if (t < STAGES) MBARRIER_INIT(mbase + 8u * t, 1u);
    if (t < 16) sbuf[STAGES * CHF + t] = 0.0f;
    __syncthreads();

    float acc[2][4][4];
#pragma unroll
    for (int mt = 0; mt < 2; mt++)
#pragma unroll
        for (int nt = 0; nt < 4; nt++)
#pragma unroll
            for (int ci = 0; ci < 4; ci++) acc[mt][nt][ci] = 0.0f;

    // ---- prologue: issue chunks 0..2 ----
    if (t == 0) {
#pragma unroll
        for (int s = 0; s < STAGES - 1; s++) {
            MBARRIER_EXPECT_TX(mbase + 8u * s, (uint32_t)CHB);
            TMA_BULK_1D(sbase + (uint32_t)(s * CHB), xq + (size_t)s * CHF,
                        (uint32_t)CHB, mbase + 8u * s);
        }
    }

    // ---- main loop: 16 chunks, 3 TMAs in flight, 1 syncthreads/iter ----
    for (int ch = 0; ch < NCH; ch++) {
        // slot (ch+3)%4 was freed by the sync at end of iter ch-1
        if (t == 0 && ch + STAGES - 1 < NCH) {
            const int s = ch + STAGES - 1;
            const uint32_t slot = (uint32_t)(s & (STAGES - 1));
            MBARRIER_EXPECT_TX(mbase + 8u * slot, (uint32_t)CHB);
            TMA_BULK_1D(sbase + slot * (uint32_t)CHB, xq + (size_t)s * CHF,
                        (uint32_t)CHB, mbase + 8u * slot);
        }

        MBARRIER_WAIT_PARITY(mbase + 8u * (uint32_t)(ch & (STAGES - 1)),
                             (uint32_t)((ch >> 2) & 1));

        const float* bc = sbuf + (ch & (STAGES - 1)) * CHF;
#pragma unroll
        for (int kb = 0; kb < 4; kb++) {      // 4 k8 steps over 32 channels
            const float* lo = bc + (kb * 8 + l4) * NDIM;
            const float* hi = lo + 4 * NDIM;
            uint32_t b0[4], b1[4];
#pragma unroll
            for (int nt = 0; nt < 4; nt++) {
                b0[nt] = __float_as_uint(lo[n0f + nt * 8]);
                b1[nt] = __float_as_uint(hi[n0f + nt * 8]);
            }
#pragma unroll
            for (int mt = 0; mt < 2; mt++) {
                const uint32_t a0 = __float_as_uint(lo[m0 + mt * 16]);
                const uint32_t a1 = __float_as_uint(lo[m0 + mt * 16 + 8]);
                const uint32_t a2 = __float_as_uint(hi[m0 + mt * 16]);
                const uint32_t a3 = __float_as_uint(hi[m0 + mt * 16 + 8]);
#pragma unroll
                for (int nt = 0; nt < 4; nt++)
                    mma8(acc[mt][nt], a0, a1, a2, a3, b0[nt], b1[nt]);
            }
        }
        __syncthreads();                      // all warps done reading this slot
    }

    // ---- write 49x49 partial Gram ----
    {
        float* __restrict__ gp = g_partial[cta];
#pragma unroll
        for (int mt = 0; mt < 2; mt++)
#pragma unroll
            for (int nt = 0; nt < 4; nt++) {
                const int rr = qm * 32 + mt * 16 + ld4;
                const int cc = qn * 32 + nt * 8 + 2 * l4;
                const float* a = acc[mt][nt];
                if (rr < NDIM) {
                    if (cc < NDIM)     gp[rr * NDIM + cc]     = a[0];
                    if (cc + 1 < NDIM) gp[rr * NDIM + cc + 1] = a[1];
                }
                if (rr + 8 < NDIM) {
                    if (cc < NDIM)     gp[(rr + 8) * NDIM + cc]     = a[2];
                    if (cc + 1 < NDIM) gp[(rr + 8) * NDIM + cc + 1] = a[3];
                }
            }
    }
    __syncthreads();
    __threadfence();
    if (t == 0) scomm = atomicAdd(&g_cnt[b], 1);
    __syncthreads();
    if (scomm != NQ - 1) return;              // not the last partial of this batch

    // ================= last arriver: power iteration for batch b =================
    __threadfence();
    {
        const float* __restrict__ p0 = g_partial[(b << 2) + 0];
        const float* __restrict__ p1 = g_partial[(b << 2) + 1];
        const float* __restrict__ p2 = g_partial[(b << 2) + 2];
        const float* __restrict__ p3 = g_partial[(b << 2) + 3];
        for (int i = t; i < NDIM * NDIM; i += THREADS)
            sA[i] = (__ldcg(p0 + i) + __ldcg(p1 + i)) +
                    (__ldcg(p2 + i) + __ldcg(p3 + i));
    }
    if (t < NDIM) sx[t] = x0[b * NDIM + t];
    __syncthreads();

    // PI-1: largest eigenvalue of ATA
    for (int it = 0; it < 9; it++) {
        float y = 0.0f;
        if (t < NDIM) {
            const float* __restrict__ rA = &sA[t * NDIM];
#pragma unroll
            for (int m = 0; m < NDIM; m++) y = fmaf(rA[m], sx[m], y);
        }
        const float n2  = reduce49(y * y, t, sred);
        const float nrm = fmaxf(sqrtf(n2), EPSV);
        if (t < NDIM) sx[t] = y / nrm;
        __syncthreads();
    }
    float y = 0.0f, xv = 0.0f;
    if (t < NDIM) {
        xv = sx[t];
        const float* __restrict__ rA = &sA[t * NDIM];
#pragma unroll
        for (int m = 0; m < NDIM; m++) y = fmaf(rA[m], sx[m], y);
    }
    float num = reduce49(y * xv, t, sred);
    float den = reduce49(xv * xv, t, sred);
    const float largest = num / den;

    // PI-2 on (ATA - largest*I), warm-started from x1
    for (int it = 0; it < 9; it++) {
        float ys = 0.0f;
        if (t < NDIM) {
            const float* __restrict__ rA = &sA[t * NDIM];
#pragma unroll
            for (int m = 0; m < NDIM; m++) ys = fmaf(rA[m], sx[m], ys);
            ys -= largest * sx[t];
        }
        const float n2  = reduce49(ys * ys, t, sred);
        const float nrm = fmaxf(sqrtf(n2), EPSV);
        if (t < NDIM) sx[t] = ys / nrm;
        __syncthreads();
    }
    y = 0.0f; xv = 0.0f;
    if (t < NDIM) {
        xv = sx[t];
        const float* __restrict__ rA = &sA[t * NDIM];
#pragma unroll
        for (int m = 0; m < NDIM; m++) y = fmaf(rA[m], sx[m], y);
        y -= largest * xv;
    }
    num = reduce49(y * xv, t, sred);
    den = reduce49(xv * xv, t, sred);
    const float smallest = (num / den) + largest;

    if (t == 0) {
        const float r = largest / smallest - 1.0f;
        g_penalty[b] = r * r;                 // BETA = 1
    }
    __threadfence();
    if (t == 0) scomm = atomicAdd(&g_cnt_all, 1);
    __syncthreads();
    if (scomm != BATCH - 1) return;           // not the global last batch

    // ================= global last arriver: deterministic finalize =================
    __threadfence();
    sA[t] = __ldcg(&g_penalty[t]) + __ldcg(&g_penalty[t + 128]);
    __syncthreads();
#pragma unroll
    for (int off = 64; off > 0; off >>= 1) {
        if (t < off) sA[t] += sA[t + off];
        __syncthreads();
    }
    if (t == 0) out[0] = sA[0] * (1.0f / (float)BATCH);

    // reset counters for the next graph replay
    g_cnt[t] = 0;
    g_cnt[t + 128] = 0;
    if (t == 0) g_cnt_all = 0;
}

extern "C" void kernel_launch(void* const* d_in, const int* in_sizes, int n_in,
                              void* d_out, int out_size) {
    const float* x  = (const float*)d_in[0];   // [256, 2048, 7, 7]
    const float* x0 = (const float*)d_in[1];   // [256, 49, 1]
    float* out = (float*)d_out;

    ofp_fused<<<NCTA, THREADS>>>(x, x0, out);
}

// round 13
// speedup vs baseline: 1.0837x; 1.0837x over previous
#include <cuda_runtime.h>
#include <cstdint>

// Fixed problem: x [256,2048,7,7] fp32, x0 [256,49,1] fp32, out scalar fp32
#define BATCH   256
#define NQ      4                     // K-split partials per batch
#define NCTA    (BATCH * NQ)          // 1024
#define KQ      512                   // channels per CTA
#define KCH     32                    // channels per chunk
#define NCH     (KQ / KCH)            // 16 chunks
#define NDIM    49
#define CHF     (KCH * NDIM)          // 1568 floats per chunk
#define CHB     (CHF * 4)             // 6272 bytes (16B multiple)
#define STAGES  4
#define THREADS 128
#define EPSV    1e-12f

__device__ float g_partial[NCTA][NDIM * NDIM];
__device__ float g_penalty[BATCH];

static __device__ __forceinline__ uint32_t smem_u32(const void* p) {
    uint32_t a;
    asm("{ .reg .u64 t; cvta.to.shared.u64 t, %1; cvt.u32.u64 %0, t; }" : "=r"(a) : "l"(p));
    return a;
}

#define MBARRIER_INIT(addr, cnt) \
    asm volatile("mbarrier.init.shared.b64 [%0], %1;" :: "r"(addr), "r"(cnt) : "memory")
#define MBARRIER_ARRIVE(addr) \
    asm volatile("mbarrier.arrive.shared.b64 _, [%0];" :: "r"(addr) : "memory")
#define MBARRIER_EXPECT_TX(addr, bytes) \
    asm volatile("mbarrier.arrive.expect_tx.shared.b64 _, [%0], %1;" \
                 :: "r"(addr), "r"(bytes) : "memory")
#define TMA_BULK_1D(dst, src, bytes, mbar) \
    asm volatile("cp.async.bulk.shared::cta.global.mbarrier::complete_tx::bytes " \
                 "[%0], [%1], %2, [%3];" \
                 :: "r"(dst), "l"(src), "r"(bytes), "r"(mbar) : "memory")

#define MBARRIER_WAIT_PARITY(addr, par) do {                                        \
    uint32_t _m = (addr), _p = (par), _d;                                           \
    asm volatile("{\n\t.reg .pred p;\n\t"                                           \
        "mbarrier.try_wait.parity.acquire.cta.shared::cta.b64 p, [%1], %2;\n\t"     \
        "selp.b32 %0, 1, 0, p;\n\t}"                                                \
        : "=r"(_d) : "r"(_m), "r"(_p) : "memory");                                  \
    if (!_d) {                                                                      \
        asm volatile("{\n\t.reg .pred P1;\n\t"                                      \
            "WL_%=:\n\t"                                                            \
            "mbarrier.try_wait.parity.acquire.cta.shared::cta.b64 P1, [%0], %1, 0x989680;\n\t" \
            "@P1 bra.uni WD_%=;\n\t"                                                \
            "bra.uni WL_%=;\n\t"                                                    \
            "WD_%=:\n\t}"                                                           \
            :: "r"(_m), "r"(_p) : "memory");                                        \
    }                                                                               \
} while (0)

// m16n8k8 tf32 mma on raw fp32 bits (HW truncates to tf32). sm_80 PTX.
static __device__ __forceinline__ void mma8(float* c,
    uint32_t a0, uint32_t a1, uint32_t a2, uint32_t a3,
    uint32_t b0, uint32_t b1)
{
    asm("mma.sync.aligned.m16n8k8.row.col.f32.tf32.tf32.f32 "
        "{%0,%1,%2,%3}, {%4,%5,%6,%7}, {%8,%9}, {%0,%1,%2,%3};"
        : "+f"(c[0]), "+f"(c[1]), "+f"(c[2]), "+f"(c[3])
        : "r"(a0), "r"(a1), "r"(a2), "r"(a3), "r"(b0), "r"(b1));
}

// ============================ kernel 1: Gram ============================
__global__ void __launch_bounds__(THREADS, 8)
ofp_gram(const float* __restrict__ x)
{
    __shared__ __align__(16) float sbuf[STAGES * CHF + 16];  // +16 zero pad for overreads
    __shared__ __align__(8) unsigned long long fullb[STAGES];
    __shared__ __align__(8) unsigned long long emptyb[STAGES];

    const int t    = threadIdx.x;
    const int lane = t & 31, wid = t >> 5;
    const int l4   = lane & 3, ld4 = lane >> 2;
    const int cta  = blockIdx.x;
    const int b    = cta >> 2, q = cta & 3;
    const int qm   = wid >> 1, qn = wid & 1;  // warp's 32x32 quadrant
    const int m0   = qm * 32 + ld4;
    const int n0f  = qn * 32 + ld4;

    const float* __restrict__ xq =
        x + (size_t)b * (2048 * NDIM) + (size_t)q * (KQ * NDIM);

    const uint32_t sbase = smem_u32(sbuf);
    const uint32_t fbase = smem_u32(fullb);
    const uint32_t ebase = smem_u32(emptyb);

    if (t < STAGES) {
        MBARRIER_INIT(fbase + 8u * t, 1u);    // completes via expect_tx + TMA tx
        MBARRIER_INIT(ebase + 8u * t, 4u);    // one arrive per warp
    }
    if (t < 16) sbuf[STAGES * CHF + t] = 0.0f;
    __syncthreads();                          // the only block barrier

    float acc[2][4][4];
#pragma unroll
    for (int mt = 0; mt < 2; mt++)
#pragma unroll
        for (int nt = 0; nt < 4; nt++)
#pragma unroll
            for (int ci = 0; ci < 4; ci++) acc[mt][nt][ci] = 0.0f;

    // prologue: issue chunks 0..2
    if (t == 0) {
#pragma unroll
        for (int s = 0; s < STAGES - 1; s++) {
            MBARRIER_EXPECT_TX(fbase + 8u * s, (uint32_t)CHB);
            TMA_BULK_1D(sbase + (uint32_t)(s * CHB), xq + (size_t)s * CHF,
                        (uint32_t)CHB, fbase + 8u * s);
        }
    }

    // main loop: no __syncthreads, warps free-run on mbarrier pairs
    for (int ch = 0; ch < NCH; ch++) {
        const uint32_t slot = (uint32_t)(ch & (STAGES - 1));

        if (t == 0 && ch + STAGES - 1 < NCH) {
            const int s = ch + STAGES - 1;
            const uint32_t sl = (uint32_t)(s & (STAGES - 1));
            if (s >= STAGES)  // slot consumed before: wait its empty flip
                MBARRIER_WAIT_PARITY(ebase + 8u * sl, (uint32_t)(((s - STAGES) >> 2) & 1));
            MBARRIER_EXPECT_TX(fbase + 8u * sl, (uint32_t)CHB);
            TMA_BULK_1D(sbase + sl * (uint32_t)CHB, xq + (size_t)s * CHF,
                        (uint32_t)CHB, fbase + 8u * sl);
        }

        MBARRIER_WAIT_PARITY(fbase + 8u * slot, (uint32_t)((ch >> 2) & 1));

        const float* bc = sbuf + slot * CHF;
#pragma unroll
        for (int kb = 0; kb < 4; kb++) {      // 4 k8 steps over 32 channels
            const float* lo = bc + (kb * 8 + l4) * NDIM;
            const float* hi = lo + 4 * NDIM;
            uint32_t b0[4], b1[4];
#pragma unroll
            for (int nt = 0; nt < 4; nt++) {
                b0[nt] = __float_as_uint(lo[n0f + nt * 8]);
                b1[nt] = __float_as_uint(hi[n0f + nt * 8]);
            }
#pragma unroll
            for (int mt = 0; mt < 2; mt++) {
                const uint32_t a0 = __float_as_uint(lo[m0 + mt * 16]);
                const uint32_t a1 = __float_as_uint(lo[m0 + mt * 16 + 8]);
                const uint32_t a2 = __float_as_uint(hi[m0 + mt * 16]);
                const uint32_t a3 = __float_as_uint(hi[m0 + mt * 16 + 8]);
#pragma unroll
                for (int nt = 0; nt < 4; nt++)
                    mma8(acc[mt][nt], a0, a1, a2, a3, b0[nt], b1[nt]);
            }
        }
        __syncwarp();
        if (lane == 0) MBARRIER_ARRIVE(ebase + 8u * slot);   // this warp done with slot
    }

    // write 49x49 partial Gram
    float* __restrict__ gp = g_partial[cta];
#pragma unroll
    for (int mt = 0; mt < 2; mt++)
#pragma unroll
        for (int nt = 0; nt < 4; nt++) {
            const int rr = qm * 32 + mt * 16 + ld4;
            const int cc = qn * 32 + nt * 8 + 2 * l4;
            const float* a = acc[mt][nt];
            if (rr < NDIM) {
                if (cc < NDIM)     gp[rr * NDIM + cc]     = a[0];
                if (cc + 1 < NDIM) gp[rr * NDIM + cc + 1] = a[1];
            }
            if (rr + 8 < NDIM) {
                if (cc < NDIM)     gp[(rr + 8) * NDIM + cc]     = a[2];
                if (cc + 1 < NDIM) gp[(rr + 8) * NDIM + cc + 1] = a[3];
            }
        }
}

// ============================ kernel 2: power iteration ============================
// Block-wide sum over first 49 lanes' values (all 128 threads call).
static __device__ __forceinline__ float reduce49(float v, int t, float* sarr) {
    if (t < 64) sarr[t] = (t < NDIM) ? v : 0.0f;
    __syncthreads();
    if (t < 32) {
        float r = sarr[t] + sarr[t + 32];
        r += __shfl_xor_sync(0xffffffffu, r, 16);
        r += __shfl_xor_sync(0xffffffffu, r, 8);
        r += __shfl_xor_sync(0xffffffffu, r, 4);
        r += __shfl_xor_sync(0xffffffffu, r, 2);
        r += __shfl_xor_sync(0xffffffffu, r, 1);
        if (t == 0) sarr[0] = r;
    }
    __syncthreads();
    float out = sarr[0];
    __syncthreads();
    return out;
}

__global__ void __launch_bounds__(THREADS)
ofp_pi(const float* __restrict__ x0)
{
    __shared__ float sA[NDIM * NDIM];
    __shared__ float sx[64];
    __shared__ float sred[64];

    const int t = threadIdx.x;
    const int b = blockIdx.x;

    {
        const float* __restrict__ p0 = g_partial[(b << 2) + 0];
        const float* __restrict__ p1 = g_partial[(b << 2) + 1];
        const float* __restrict__ p2 = g_partial[(b << 2) + 2];
        const float* __restrict__ p3 = g_partial[(b << 2) + 3];
        for (int i = t; i < NDIM * NDIM; i += THREADS)
            sA[i] = (p0[i] + p1[i]) + (p2[i] + p3[i]);
    }
    if (t < NDIM) sx[t] = x0[b * NDIM + t];
    __syncthreads();

    // PI-1: largest eigenvalue of ATA
    for (int it = 0; it < 9; it++) {
        float y = 0.0f;
        if (t < NDIM) {
            const float* __restrict__ rA = &sA[t * NDIM];
#pragma unroll
            for (int m = 0; m < NDIM; m++) y = fmaf(rA[m], sx[m], y);
        }
        const float n2  = reduce49(y * y, t, sred);
        const float nrm = fmaxf(sqrtf(n2), EPSV);
        if (t < NDIM) sx[t] = y / nrm;
        __syncthreads();
    }
    float y = 0.0f, xv = 0.0f;
    if (t < NDIM) {
        xv = sx[t];
        const float* __restrict__ rA = &sA[t * NDIM];
#pragma unroll
        for (int m = 0; m < NDIM; m++) y = fmaf(rA[m], sx[m], y);
    }
    float num = reduce49(y * xv, t, sred);
    float den = reduce49(xv * xv, t, sred);
    const float largest = num / den;

    // PI-2 on (ATA - largest*I), warm-started from x1
    for (int it = 0; it < 9; it++) {
        float ys = 0.0f;
        if (t < NDIM) {
            const float* __restrict__ rA = &sA[t * NDIM];
#pragma unroll
            for (int m = 0; m < NDIM; m++) ys = fmaf(rA[m], sx[m], ys);
            ys -= largest * sx[t];
        }
        const float n2  = reduce49(ys * ys, t, sred);
        const float nrm = fmaxf(sqrtf(n2), EPSV);
        if (t < NDIM) sx[t] = ys / nrm;
        __syncthreads();
    }
    y = 0.0f; xv = 0.0f;
    if (t < NDIM) {
        xv = sx[t];
        const float* __restrict__ rA = &sA[t * NDIM];
#pragma unroll
        for (int m = 0; m < NDIM; m++) y = fmaf(rA[m], sx[m], y);
        y -= largest * xv;
    }
    num = reduce49(y * xv, t, sred);
    den = reduce49(xv * xv, t, sred);
    const float smallest = (num / den) + largest;

    if (t == 0) {
        const float r = largest / smallest - 1.0f;
        g_penalty[b] = r * r;                 // BETA = 1
    }
}

// ============================ kernel 3: finalize ============================
__global__ void ofp_finalize(float* __restrict__ out) {
    __shared__ float s[BATCH];
    const int t = threadIdx.x;
    s[t] = g_penalty[t];
    __syncthreads();
#pragma unroll
    for (int off = BATCH / 2; off > 0; off >>= 1) {
        if (t < off) s[t] += s[t + off];
        __syncthreads();
    }
    if (t == 0) out[0] = s[0] * (1.0f / (float)BATCH);
}

extern "C" void kernel_launch(void* const* d_in, const int* in_sizes, int n_in,
                              void* d_out, int out_size) {
    const float* x  = (const float*)d_in[0];   // [256, 2048, 7, 7]
    const float* x0 = (const float*)d_in[1];   // [256, 49, 1]
    float* out = (float*)d_out;

    ofp_gram<<<NCTA, THREADS>>>(x);
    ofp_pi<<<BATCH, THREADS>>>(x0);
    ofp_finalize<<<1, BATCH>>>(out);
}

// round 14
// speedup vs baseline: 1.1515x; 1.0625x over previous
#include <cuda_runtime.h>
#include <cstdint>

// Fixed problem: x [256,2048,7,7] fp32, x0 [256,49,1] fp32, out scalar fp32
#define BATCH   256
#define NQ      4                     // K-split partials per batch
#define NCTA    (BATCH * NQ)          // 1024
#define KQ      512                   // channels per CTA
#define KCH     32                    // channels per chunk
#define NCH     (KQ / KCH)            // 16 chunks
#define NDIM    49
#define CHF     (KCH * NDIM)          // 1568 floats per chunk
#define CHB     (CHF * 4)             // 6272 bytes (16B multiple)
#define STAGES  4
#define THREADS 128
#define EPSV    1e-12f

__device__ float g_partial[NCTA][NDIM * NDIM];
__device__ float g_penalty[BATCH];
__device__ int   g_cnt_all;           // zero-init; reset by last arriver

static __device__ __forceinline__ uint32_t smem_u32(const void* p) {
    uint32_t a;
    asm("{ .reg .u64 t; cvta.to.shared.u64 t, %1; cvt.u32.u64 %0, t; }" : "=r"(a) : "l"(p));
    return a;
}

#define MBARRIER_INIT(addr, cnt) \
    asm volatile("mbarrier.init.shared.b64 [%0], %1;" :: "r"(addr), "r"(cnt) : "memory")
#define MBARRIER_ARRIVE(addr) \
    asm volatile("mbarrier.arrive.shared.b64 _, [%0];" :: "r"(addr) : "memory")
#define MBARRIER_EXPECT_TX(addr, bytes) \
    asm volatile("mbarrier.arrive.expect_tx.shared.b64 _, [%0], %1;" \
                 :: "r"(addr), "r"(bytes) : "memory")
#define TMA_BULK_1D(dst, src, bytes, mbar) \
    asm volatile("cp.async.bulk.shared::cta.global.mbarrier::complete_tx::bytes " \
                 "[%0], [%1], %2, [%3];" \
                 :: "r"(dst), "l"(src), "r"(bytes), "r"(mbar) : "memory")

#define MBARRIER_WAIT_PARITY(addr, par) do {                                        \
    uint32_t _m = (addr), _p = (par), _d;                                           \
    asm volatile("{\n\t.reg .pred p;\n\t"                                           \
        "mbarrier.try_wait.parity.acquire.cta.shared::cta.b64 p, [%1], %2;\n\t"     \
        "selp.b32 %0, 1, 0, p;\n\t}"                                                \
        : "=r"(_d) : "r"(_m), "r"(_p) : "memory");                                  \
    if (!_d) {                                                                      \
        asm volatile("{\n\t.reg .pred P1;\n\t"                                      \
            "WL_%=:\n\t"                                                            \
            "mbarrier.try_wait.parity.acquire.cta.shared::cta.b64 P1, [%0], %1, 0x989680;\n\t" \
            "@P1 bra.uni WD_%=;\n\t"                                                \
            "bra.uni WL_%=;\n\t"                                                    \
            "WD_%=:\n\t}"                                                           \
            :: "r"(_m), "r"(_p) : "memory");                                        \
    }                                                                               \
} while (0)

// m16n8k8 tf32 mma on raw fp32 bits (HW truncates to tf32). sm_80 PTX.
static __device__ __forceinline__ void mma8(float* c,
    uint32_t a0, uint32_t a1, uint32_t a2, uint32_t a3,
    uint32_t b0, uint32_t b1)
{
    asm("mma.sync.aligned.m16n8k8.row.col.f32.tf32.tf32.f32 "
        "{%0,%1,%2,%3}, {%4,%5,%6,%7}, {%8,%9}, {%0,%1,%2,%3};"
        : "+f"(c[0]), "+f"(c[1]), "+f"(c[2]), "+f"(c[3])
        : "r"(a0), "r"(a1), "r"(a2), "r"(a3), "r"(b0), "r"(b1));
}

// ============================ kernel 1: Gram (unchanged from R13) ============================
__global__ void __launch_bounds__(THREADS, 8)
ofp_gram(const float* __restrict__ x)
{
    __shared__ __align__(16) float sbuf[STAGES * CHF + 16];  // +16 zero pad for overreads
    __shared__ __align__(8) unsigned long long fullb[STAGES];
    __shared__ __align__(8) unsigned long long emptyb[STAGES];

    const int t    = threadIdx.x;
    const int lane = t & 31, wid = t >> 5;
    const int l4   = lane & 3, ld4 = lane >> 2;
    const int cta  = blockIdx.x;
    const int b    = cta >> 2, q = cta & 3;
    const int qm   = wid >> 1, qn = wid & 1;  // warp's 32x32 quadrant
    const int m0   = qm * 32 + ld4;
    const int n0f  = qn * 32 + ld4;

    const float* __restrict__ xq =
        x + (size_t)b * (2048 * NDIM) + (size_t)q * (KQ * NDIM);

    const uint32_t sbase = smem_u32(sbuf);
    const uint32_t fbase = smem_u32(fullb);
    const uint32_t ebase = smem_u32(emptyb);

    if (t < STAGES) {
        MBARRIER_INIT(fbase + 8u * t, 1u);    // completes via expect_tx + TMA tx
        MBARRIER_INIT(ebase + 8u * t, 4u);    // one arrive per warp
    }
    if (t < 16) sbuf[STAGES * CHF + t] = 0.0f;
    __syncthreads();                          // the only block barrier

    float acc[2][4][4];
#pragma unroll
    for (int mt = 0; mt < 2; mt++)
#pragma unroll
        for (int nt = 0; nt < 4; nt++)
#pragma unroll
            for (int ci = 0; ci < 4; ci++) acc[mt][nt][ci] = 0.0f;

    if (t == 0) {
#pragma unroll
        for (int s = 0; s < STAGES - 1; s++) {
            MBARRIER_EXPECT_TX(fbase + 8u * s, (uint32_t)CHB);
            TMA_BULK_1D(sbase + (uint32_t)(s * CHB), xq + (size_t)s * CHF,
                        (uint32_t)CHB, fbase + 8u * s);
        }
    }

    for (int ch = 0; ch < NCH; ch++) {
        const uint32_t slot = (uint32_t)(ch & (STAGES - 1));

        if (t == 0 && ch + STAGES - 1 < NCH) {
            const int s = ch + STAGES - 1;
            const uint32_t sl = (uint32_t)(s & (STAGES - 1));
            if (s >= STAGES)
                MBARRIER_WAIT_PARITY(ebase + 8u * sl, (uint32_t)(((s - STAGES) >> 2) & 1));
            MBARRIER_EXPECT_TX(fbase + 8u * sl, (uint32_t)CHB);
            TMA_BULK_1D(sbase + sl * (uint32_t)CHB, xq + (size_t)s * CHF,
                        (uint32_t)CHB, fbase + 8u * sl);
        }

        MBARRIER_WAIT_PARITY(fbase + 8u * slot, (uint32_t)((ch >> 2) & 1));

        const float* bc = sbuf + slot * CHF;
#pragma unroll
        for (int kb = 0; kb < 4; kb++) {
            const float* lo = bc + (kb * 8 + l4) * NDIM;
            const float* hi = lo + 4 * NDIM;
            uint32_t b0[4], b1[4];
#pragma unroll
            for (int nt = 0; nt < 4; nt++) {
                b0[nt] = __float_as_uint(lo[n0f + nt * 8]);
                b1[nt] = __float_as_uint(hi[n0f + nt * 8]);
            }
#pragma unroll
            for (int mt = 0; mt < 2; mt++) {
                const uint32_t a0 = __float_as_uint(lo[m0 + mt * 16]);
                const uint32_t a1 = __float_as_uint(lo[m0 + mt * 16 + 8]);
                const uint32_t a2 = __float_as_uint(hi[m0 + mt * 16]);
                const uint32_t a3 = __float_as_uint(hi[m0 + mt * 16 + 8]);
#pragma unroll
                for (int nt = 0; nt < 4; nt++)
                    mma8(acc[mt][nt], a0, a1, a2, a3, b0[nt], b1[nt]);
            }
        }
        __syncwarp();
        if (lane == 0) MBARRIER_ARRIVE(ebase + 8u * slot);
    }

    float* __restrict__ gp = g_partial[cta];
#pragma unroll
    for (int mt = 0; mt < 2; mt++)
#pragma unroll
        for (int nt = 0; nt < 4; nt++) {
            const int rr = qm * 32 + mt * 16 + ld4;
            const int cc = qn * 32 + nt * 8 + 2 * l4;
            const float* a = acc[mt][nt];
            if (rr < NDIM) {
                if (cc < NDIM)     gp[rr * NDIM + cc]     = a[0];
                if (cc + 1 < NDIM) gp[rr * NDIM + cc + 1] = a[1];
            }
            if (rr + 8 < NDIM) {
                if (cc < NDIM)     gp[(rr + 8) * NDIM + cc]     = a[2];
                if (cc + 1 < NDIM) gp[(rr + 8) * NDIM + cc + 1] = a[3];
            }
        }
}

// ============================ kernel 2: PI + fused finalize ============================
static __device__ __forceinline__ float warpsum(float v) {
    v += __shfl_xor_sync(0xffffffffu, v, 16);
    v += __shfl_xor_sync(0xffffffffu, v, 8);
    v += __shfl_xor_sync(0xffffffffu, v, 4);
    v += __shfl_xor_sync(0xffffffffu, v, 2);
    v += __shfl_xor_sync(0xffffffffu, v, 1);
    return v;
}

__global__ void __launch_bounds__(THREADS)
ofp_pi(const float* __restrict__ x0, float* __restrict__ out)
{
    __shared__ float sA[NDIM * NDIM];
    __shared__ float sx[64];

    const int t    = threadIdx.x;
    const int lane = t & 31, wid = t >> 5;
    const int b    = blockIdx.x;

    // cooperative sum of the 4 partial Grams
    {
        const float* __restrict__ p0 = g_partial[(b << 2) + 0];
        const float* __restrict__ p1 = g_partial[(b << 2) + 1];
        const float* __restrict__ p2 = g_partial[(b << 2) + 2];
        const float* __restrict__ p3 = g_partial[(b << 2) + 3];
        for (int i = t; i < NDIM * NDIM; i += THREADS)
            sA[i] = (p0[i] + p1[i]) + (p2[i] + p3[i]);
    }
    if (t < NDIM) sx[t] = x0[b * NDIM + t];
    if (t >= NDIM && t < 64) sx[t] = 0.0f;
    __syncthreads();

    if (wid != 0) return;                       // PI runs on warp 0 only

    // lanes own rows `lane` and (if lane<17) `lane+32`, register-resident
    const bool has2 = (lane < NDIM - 32);
    float rA0[NDIM], rA1[NDIM];
#pragma unroll
    for (int m = 0; m < NDIM; m++) {
        rA0[m] = sA[lane * NDIM + m];
        rA1[m] = has2 ? sA[(lane + 32) * NDIM + m] : 0.0f;
    }

    // PI-1: largest eigenvalue of ATA
    for (int it = 0; it < 9; it++) {
        float y0 = 0.0f, y1 = 0.0f;
#pragma unroll
        for (int m = 0; m < NDIM; m++) {
            const float xm = sx[m];
            y0 = fmaf(rA0[m], xm, y0);
            y1 = fmaf(rA1[m], xm, y1);
        }
        if (!has2) y1 = 0.0f;
        const float n2  = warpsum(y0 * y0 + y1 * y1);
        const float inv = 1.0f / fmaxf(sqrtf(n2), EPSV);
        sx[lane] = y0 * inv;
        if (has2) sx[lane + 32] = y1 * inv;
        __syncwarp();
    }
    {
        float y0 = 0.0f, y1 = 0.0f;
#pragma unroll
        for (int m = 0; m < NDIM; m++) {
            const float xm = sx[m];
            y0 = fmaf(rA0[m], xm, y0);
            y1 = fmaf(rA1[m], xm, y1);
        }
        if (!has2) y1 = 0.0f;
        const float x0v = sx[lane];
        const float x1v = has2 ? sx[lane + 32] : 0.0f;
        const float num = warpsum(y0 * x0v + y1 * x1v);
        const float den = warpsum(x0v * x0v + x1v * x1v);
        const float largest = num / den;

        // PI-2 on (ATA - largest*I), warm-started from x1
        for (int it = 0; it < 9; it++) {
            float z0 = 0.0f, z1 = 0.0f;
#pragma unroll
            for (int m = 0; m < NDIM; m++) {
                const float xm = sx[m];
                z0 = fmaf(rA0[m], xm, z0);
                z1 = fmaf(rA1[m], xm, z1);
            }
            z0 -= largest * sx[lane];
            z1 = has2 ? (z1 - largest * sx[lane + 32]) : 0.0f;
            const float n2  = warpsum(z0 * z0 + z1 * z1);
            const float inv = 1.0f / fmaxf(sqrtf(n2), EPSV);
            sx[lane] = z0 * inv;
            if (has2) sx[lane + 32] = z1 * inv;
            __syncwarp();
        }
        float z0 = 0.0f, z1 = 0.0f;
#pragma unroll
        for (int m = 0; m < NDIM; m++) {
            const float xm = sx[m];
            z0 = fmaf(rA0[m], xm, z0);
            z1 = fmaf(rA1[m], xm, z1);
        }
        const float u0 = sx[lane];
        const float u1 = has2 ? sx[lane + 32] : 0.0f;
        z0 -= largest * u0;
        z1 = has2 ? (z1 - largest * u1) : 0.0f;
        const float num2 = warpsum(z0 * u0 + z1 * u1);
        const float den2 = warpsum(u0 * u0 + u1 * u1);
        const float smallest = (num2 / den2) + largest;

        if (lane == 0) {
            const float r = largest / smallest - 1.0f;
            g_penalty[b] = r * r;               // BETA = 1
        }
    }

    // -------- fused finalize: last-arriver warp sums all penalties --------
    __threadfence();
    int old = 0;
    if (lane == 0) old = atomicAdd(&g_cnt_all, 1);
    old = __shfl_sync(0xffffffffu, old, 0);
    if (old != BATCH - 1) return;

    __threadfence();
    float s = 0.0f;
#pragma unroll
    for (int k = 0; k < BATCH / 32; k++)        // fixed order -> deterministic
        s += __ldcg(&g_penalty[lane + 32 * k]);
    s = warpsum(s);
    if (lane == 0) {
        out[0] = s * (1.0f / (float)BATCH);
        g_cnt_all = 0;                          // reset for graph replay
    }
}

extern "C" void kernel_launch(void* const* d_in, const int* in_sizes, int n_in,
                              void* d_out, int out_size) {
    const float* x  = (const float*)d_in[0];   // [256, 2048, 7, 7]
    const float* x0 = (const float*)d_in[1];   // [256, 49, 1]
    float* out = (float*)d_out;

    ofp_gram<<<NCTA, THREADS>>>(x);
    ofp_pi<<<BATCH, THREADS>>>(x0, out);
}